// round 2
// baseline (speedup 1.0000x reference)
#include <cuda_runtime.h>
#include <cuda_fp16.h>
#include <cstdint>

// Problem constants (fixed shapes)
#define BB   512
#define NN   100
#define CC   256
#define KK   3
#define NJ   103      // N + K
#define DYW  104      // sDy row stride (floats)
#define KC   32       // k-chunk for GEMM1

// ---------- packed f32x2 helpers (sm_103a) ----------
__device__ __forceinline__ uint64_t pack2(float s) {
    uint64_t r;
    asm("mov.b64 %0, {%1, %1};" : "=l"(r) : "r"(__float_as_uint(s)));
    return r;
}
__device__ __forceinline__ void ffma2(uint64_t& d, uint64_t a, uint64_t b) {
    asm("fma.rn.f32x2 %0, %1, %2, %0;" : "+l"(d) : "l"(a), "l"(b));
}
__device__ __forceinline__ void unpack2(uint64_t p, float& a, float& b) {
    asm("mov.b64 {%0, %1}, %2;" : "=f"(a), "=f"(b) : "l"(p));
}
// half2 (raw u32) -> packed f32x2 (u64)
__device__ __forceinline__ uint64_t h2f2(uint32_t h) {
    uint64_t r;
    asm("{.reg .f32 lo, hi; .reg .b16 a, b;\n\t"
        " mov.b32 {a, b}, %1;\n\t"
        " cvt.f32.f16 lo, a;\n\t"
        " cvt.f32.f16 hi, b;\n\t"
        " mov.b64 %0, {lo, hi};}\n\t"
        : "=l"(r) : "r"(h));
    return r;
}

__global__ void __launch_bounds__(256, 2)
dysepconv_fused_kernel(const float* __restrict__ gq,
                       const float* __restrict__ gv,
                       const float* __restrict__ gW,
                       const float* __restrict__ gbias,
                       const float* __restrict__ ggamma,
                       const float* __restrict__ gbeta,
                       float* __restrict__ gout)
{
    extern __shared__ float smem[];
    // layout:
    //   sDy    : 104 x 104 fp32                    (43264 B)
    //   region : 51200 B, time-shared:
    //     stage1: sQc 104x32 f32 | sWp 16x104x2 f32 | sBias 104 f32
    //     stage2/3: sDepth 100x256 fp16
    float* sDy = smem;                               // 10816 floats
    float* dyn = smem + 104 * DYW;
    float* sQc   = dyn;                              // 3328 floats
    float* sWp   = dyn + 3328;                       // 3328 floats (k-pair interleaved)
    float* sBias = dyn + 6656;                       // 104 floats
    __half* sDepth = (__half*)dyn;                   // 25600 halfs

    const int tid  = threadIdx.x;
    const int lane = tid & 31;
    const int wid  = tid >> 5;
    const int b    = blockIdx.x;

    const float* q    = gq + (size_t)b * NN * CC;
    const float* v    = gv + (size_t)b * NN * CC;
    float*       outp = gout + (size_t)b * NN * CC;

    if (tid < 104) sBias[tid] = (tid < NJ) ? gbias[tid] : 0.0f;

    // =========================================================
    // Stage 1: dy = q @ W + bias   (100x256 @ 256x103 -> sDy 104x104)
    // f32x2 lanes = (k even, k odd) partial sums; reduce lo+hi at store.
    // thread: rows r0..r0+12 (warp-uniform), cols {lane + 32*j}, j<4 (col<104)
    // =========================================================
    const int r0 = wid * 13;
    uint64_t accA[13][4];
    #pragma unroll
    for (int i = 0; i < 13; i++)
        #pragma unroll
        for (int j = 0; j < 4; j++) accA[i][j] = 0ull;

    for (int kc = 0; kc < CC; kc += KC) {
        // q chunk: 100 rows x 32 cols (800 float4)
        #pragma unroll
        for (int it = 0; it < 4; it++) {
            int idx = tid + it * 256;
            if (idx < 800) {
                int r = idx >> 3, g = idx & 7;
                *(float4*)&sQc[r * KC + g * 4] =
                    *(const float4*)&q[r * CC + kc + g * 4];
            }
        }
        // W chunk -> k-pair interleaved: sWp[(k>>1)*208 + j*2 + (k&1)]
        #pragma unroll
        for (int it = 0; it < 16; it++) {
            int idx = tid + it * 256;
            int k = idx >> 7, j = idx & 127;
            if (j < 104) {
                float w = (j < NJ) ? gW[(kc + k) * NJ + j] : 0.0f;
                sWp[(k >> 1) * 208 + j * 2 + (k & 1)] = w;
            }
        }
        __syncthreads();

        #pragma unroll 1
        for (int k2 = 0; k2 < 16; k2++) {
            uint64_t w0 = *(const uint64_t*)&sWp[k2 * 208 + (lane     ) * 2];
            uint64_t w1 = *(const uint64_t*)&sWp[k2 * 208 + (lane + 32) * 2];
            uint64_t w2 = *(const uint64_t*)&sWp[k2 * 208 + (lane + 64) * 2];
            uint64_t w3 = *(const uint64_t*)&sWp[k2 * 208 + (lane + 96) * 2];
            #pragma unroll
            for (int i = 0; i < 13; i++) {
                uint64_t qp = *(const uint64_t*)&sQc[(r0 + i) * KC + k2 * 2];
                ffma2(accA[i][0], qp, w0);
                ffma2(accA[i][1], qp, w1);
                ffma2(accA[i][2], qp, w2);
                ffma2(accA[i][3], qp, w3);
            }
        }
        __syncthreads();
    }

    // reduce k-parity + bias, store dy
    #pragma unroll
    for (int i = 0; i < 13; i++) {
        #pragma unroll
        for (int j = 0; j < 4; j++) {
            int col = lane + 32 * j;
            if (col < 104) {
                float lo, hi;
                unpack2(accA[i][j], lo, hi);
                sDy[(r0 + i) * DYW + col] = lo + hi + sBias[col];
            }
        }
    }
    __syncthreads();

    // =========================================================
    // Stage 2: depth[m][c] = relu(dw0*v[c-1]+dw1*v[c]+dw2*v[c+1]) -> fp16
    // =========================================================
    #pragma unroll 1
    for (int it = 0; it < 25; it++) {
        int idx = tid + it * 256;
        int r = idx >> 6, g = idx & 63;
        int c0 = g * 4;
        const float* vr = v + r * CC;
        float4 vv = *(const float4*)&vr[c0];
        float vl = (c0 > 0)   ? vr[c0 - 1] : 0.0f;
        float vh = (c0 < 252) ? vr[c0 + 4] : 0.0f;
        float d0 = sDy[r * DYW + 0];
        float d1 = sDy[r * DYW + 1];
        float d2 = sDy[r * DYW + 2];
        float ox = fmaxf(d0 * vl   + d1 * vv.x + d2 * vv.y, 0.0f);
        float oy = fmaxf(d0 * vv.x + d1 * vv.y + d2 * vv.z, 0.0f);
        float oz = fmaxf(d0 * vv.y + d1 * vv.z + d2 * vv.w, 0.0f);
        float ow = fmaxf(d0 * vv.z + d1 * vv.w + d2 * vh,   0.0f);
        union { __half2 h[2]; uint2 u; } pk;
        pk.h[0] = __floats2half2_rn(ox, oy);
        pk.h[1] = __floats2half2_rn(oz, ow);
        *(uint2*)&sDepth[r * CC + c0] = pk.u;
    }
    __syncthreads();

    // =========================================================
    // Stage 3: out[n][c] = sum_m pw[n][m] * depth[m][c]
    // thread: rows r0..r0+12, cols {4*lane..+3} and {128+4*lane..+3}
    // =========================================================
    uint64_t acc[13][4];
    #pragma unroll
    for (int i = 0; i < 13; i++)
        #pragma unroll
        for (int j = 0; j < 4; j++) acc[i][j] = 0ull;

    const float* pwBase = sDy + r0 * DYW + KK;

    #pragma unroll 2
    for (int m = 0; m < NN; m++) {
        uint2 da = *(const uint2*)&sDepth[m * CC + 4 * lane];
        uint2 db = *(const uint2*)&sDepth[m * CC + 128 + 4 * lane];
        uint64_t p0 = h2f2(da.x);
        uint64_t p1 = h2f2(da.y);
        uint64_t p2 = h2f2(db.x);
        uint64_t p3 = h2f2(db.y);
        #pragma unroll
        for (int i = 0; i < 13; i++) {
            uint64_t pp = pack2(pwBase[i * DYW + m]);
            ffma2(acc[i][0], pp, p0);
            ffma2(acc[i][1], pp, p1);
            ffma2(acc[i][2], pp, p2);
            ffma2(acc[i][3], pp, p3);
        }
    }

    // =========================================================
    // Stage 4: LayerNorm from registers (row r0+i lives in warp wid)
    // =========================================================
    float4 g0  = *(const float4*)&ggamma[4 * lane];
    float4 g1  = *(const float4*)&ggamma[128 + 4 * lane];
    float4 be0 = *(const float4*)&gbeta[4 * lane];
    float4 be1 = *(const float4*)&gbeta[128 + 4 * lane];

    #pragma unroll
    for (int i = 0; i < 13; i++) {
        int r = r0 + i;
        if (r < NN) {
            float f[8];
            unpack2(acc[i][0], f[0], f[1]);
            unpack2(acc[i][1], f[2], f[3]);
            unpack2(acc[i][2], f[4], f[5]);
            unpack2(acc[i][3], f[6], f[7]);
            float s  = ((f[0] + f[1]) + (f[2] + f[3])) + ((f[4] + f[5]) + (f[6] + f[7]));
            float ss = ((f[0]*f[0] + f[1]*f[1]) + (f[2]*f[2] + f[3]*f[3]))
                     + ((f[4]*f[4] + f[5]*f[5]) + (f[6]*f[6] + f[7]*f[7]));
            #pragma unroll
            for (int off = 16; off >= 1; off >>= 1) {
                s  += __shfl_xor_sync(0xffffffffu, s,  off);
                ss += __shfl_xor_sync(0xffffffffu, ss, off);
            }
            float mu  = s * (1.0f / 256.0f);
            float var = ss * (1.0f / 256.0f) - mu * mu;
            float inv = rsqrtf(var + 1e-5f);
            float4 o0, o1;
            o0.x = (f[0] - mu) * inv * g0.x + be0.x;
            o0.y = (f[1] - mu) * inv * g0.y + be0.y;
            o0.z = (f[2] - mu) * inv * g0.z + be0.z;
            o0.w = (f[3] - mu) * inv * g0.w + be0.w;
            o1.x = (f[4] - mu) * inv * g1.x + be1.x;
            o1.y = (f[5] - mu) * inv * g1.y + be1.y;
            o1.z = (f[6] - mu) * inv * g1.z + be1.z;
            o1.w = (f[7] - mu) * inv * g1.w + be1.w;
            *(float4*)&outp[r * CC + 4 * lane] = o0;
            *(float4*)&outp[r * CC + 128 + 4 * lane] = o1;
        }
    }
}

extern "C" void kernel_launch(void* const* d_in, const int* in_sizes, int n_in,
                              void* d_out, int out_size) {
    const float* q     = (const float*)d_in[0];
    const float* v     = (const float*)d_in[1];
    const float* W     = (const float*)d_in[2];
    const float* bias  = (const float*)d_in[3];
    const float* gamma = (const float*)d_in[4];
    const float* beta  = (const float*)d_in[5];
    float* out = (float*)d_out;

    const int smem_bytes = 104 * DYW * 4 + 51200;   // 43264 + 51200 = 94464 B
    cudaFuncSetAttribute(dysepconv_fused_kernel,
                         cudaFuncAttributeMaxDynamicSharedMemorySize, smem_bytes);
    dysepconv_fused_kernel<<<BB, 256, smem_bytes>>>(q, v, W, bias, gamma, beta, out);
}

// round 3
// speedup vs baseline: 1.2286x; 1.2286x over previous
#include <cuda_runtime.h>
#include <cuda_fp16.h>
#include <cstdint>

// shapes
#define BB 512
#define NN 100
#define CC 256
#define NJ 103

// fp16 row strides (elements) — all row pitches multiples of 8 fp16 (16B) for ldmatrix
#define QS  72     // sQh [112][72]
#define WS  72     // sWh (W^T) [112][72]
#define PWS 120    // pw_h [112][120]
#define DTS 120    // sDT (depth^T) [256][120]

// smem byte offsets
#define OFF_PW   0                      // 112*120*2 = 26880
#define OFF_DW   26880                  // 100*4*4   = 1600
#define OFF_BIAS 28480                  // 104*4     = 416
#define OFF_RED  28896                  // 2*16*8*2*4 = 2048
#define OFF_STG  30976                  // stage region
#define OFF_W2   (OFF_STG + 112*QS*2)   // sWh after sQh (16128)
#define SMEM_TOTAL (OFF_STG + 256*DTS*2) // 30976 + 61440 = 92416

__device__ __forceinline__ void ldsm4(uint32_t& r0, uint32_t& r1, uint32_t& r2, uint32_t& r3, uint32_t addr) {
    asm volatile("ldmatrix.sync.aligned.m8n8.x4.shared.b16 {%0,%1,%2,%3}, [%4];"
                 : "=r"(r0), "=r"(r1), "=r"(r2), "=r"(r3) : "r"(addr));
}
__device__ __forceinline__ void ldsm2(uint32_t& r0, uint32_t& r1, uint32_t addr) {
    asm volatile("ldmatrix.sync.aligned.m8n8.x2.shared.b16 {%0,%1}, [%2];"
                 : "=r"(r0), "=r"(r1) : "r"(addr));
}
__device__ __forceinline__ void mma16816(float* c, uint32_t a0, uint32_t a1, uint32_t a2, uint32_t a3,
                                         uint32_t b0, uint32_t b1) {
    asm volatile("mma.sync.aligned.m16n8k16.row.col.f32.f16.f16.f32 "
                 "{%0,%1,%2,%3}, {%4,%5,%6,%7}, {%8,%9}, {%0,%1,%2,%3};"
                 : "+f"(c[0]), "+f"(c[1]), "+f"(c[2]), "+f"(c[3])
                 : "r"(a0), "r"(a1), "r"(a2), "r"(a3), "r"(b0), "r"(b1));
}

__global__ void __launch_bounds__(256, 2)
dysepconv_mma_kernel(const float* __restrict__ gq,
                     const float* __restrict__ gv,
                     const float* __restrict__ gW,
                     const float* __restrict__ gbias,
                     const float* __restrict__ ggamma,
                     const float* __restrict__ gbeta,
                     float* __restrict__ gout)
{
    extern __shared__ char sm[];
    __half* pw_h  = (__half*)(sm + OFF_PW);
    float*  sDw   = (float*) (sm + OFF_DW);
    float*  sBias = (float*) (sm + OFF_BIAS);
    float*  sRed  = (float*) (sm + OFF_RED);   // [2][16][8][2]
    __half* sQh   = (__half*)(sm + OFF_STG);
    __half* sWh   = (__half*)(sm + OFF_W2);
    __half* sDT   = (__half*)(sm + OFF_STG);   // aliases stage region

    const int tid  = threadIdx.x;
    const int lane = tid & 31;
    const int wid  = tid >> 5;
    const int b    = blockIdx.x;

    const float* q    = gq + (size_t)b * NN * CC;
    const float* v    = gv + (size_t)b * NN * CC;
    float*       outp = gout + (size_t)b * NN * CC;

    const uint32_t sQ_u  = (uint32_t)__cvta_generic_to_shared(sQh);
    const uint32_t sW_u  = (uint32_t)__cvta_generic_to_shared(sWh);
    const uint32_t sPW_u = (uint32_t)__cvta_generic_to_shared(pw_h);
    const uint32_t sDT_u = (uint32_t)__cvta_generic_to_shared(sDT);

    // bias + pw zero-pad (cols 100..119; benign overlap with epilogue's zero at col 100)
    if (tid < 104) sBias[tid] = (tid < NJ) ? gbias[tid] : 0.0f;
    #pragma unroll
    for (int it = 0; it < 9; it++) {
        int idx = tid + it * 256;
        if (idx < 112 * 20) pw_h[(idx / 20) * PWS + 100 + (idx % 20)] = __float2half(0.0f);
    }

    // gamma/beta for this lane's 8 output columns (fixed across rounds)
    float g8[8], be8[8];
    #pragma unroll
    for (int t = 0; t < 4; t++) {
        int col = wid * 32 + t * 8 + 2 * (lane & 3);
        g8[2 * t]      = ggamma[col];
        g8[2 * t + 1]  = ggamma[col + 1];
        be8[2 * t]     = gbeta[col];
        be8[2 * t + 1] = gbeta[col + 1];
    }

    // =========================================================
    // Stage 1: dy = q @ W + bias via HMMA.  M=112(7 m16), N=104(13 n8), K=256
    // warp tiles t = wid + 8*i, i<12, t<91; k-chunks of 64.
    // =========================================================
    float acc1[12][4];
    #pragma unroll
    for (int i = 0; i < 12; i++)
        #pragma unroll
        for (int j = 0; j < 4; j++) acc1[i][j] = 0.0f;

    for (int kc = 0; kc < CC; kc += 64) {
        // stage q chunk -> sQh [112][64] fp16 (rows >=100 zero)
        #pragma unroll
        for (int it = 0; it < 7; it++) {
            int idx = tid + it * 256;          // 1792 float4 groups
            int r = idx >> 4, kq = idx & 15;
            float4 f4 = make_float4(0.f, 0.f, 0.f, 0.f);
            if (r < NN) f4 = *(const float4*)&q[r * CC + kc + kq * 4];
            __half2 h01 = __floats2half2_rn(f4.x, f4.y);
            __half2 h23 = __floats2half2_rn(f4.z, f4.w);
            *(uint2*)&sQh[r * QS + kq * 4] = make_uint2(
                *(uint32_t*)&h01, *(uint32_t*)&h23);
        }
        // stage W^T chunk -> sWh[n][k], n<103 real, rest zero
        #pragma unroll
        for (int it = 0; it < 28; it++) {
            int idx = tid + it * 256;          // 7168
            int k = idx / 112, n = idx % 112;
            float w = (n < NJ) ? gW[(kc + k) * NJ + n] : 0.0f;
            sWh[n * WS + k] = __float2half(w);
        }
        __syncthreads();

        #pragma unroll
        for (int i = 0; i < 12; i++) {
            int t = wid + 8 * i;
            if (t < 91) {
                int mt = t / 13, nt = t % 13;
                uint32_t abase = sQ_u + ((mt * 16 + (lane & 15)) * QS + (lane >> 4) * 8) * 2;
                uint32_t bbase = sW_u + ((nt * 8 + (lane & 7)) * WS + ((lane >> 3) & 1) * 8) * 2;
                #pragma unroll
                for (int ks = 0; ks < 4; ks++) {
                    uint32_t a0, a1, a2, a3, b0, b1;
                    ldsm4(a0, a1, a2, a3, abase + ks * 32);
                    ldsm2(b0, b1, bbase + ks * 32);
                    mma16816(acc1[i], a0, a1, a2, a3, b0, b1);
                }
            }
        }
        __syncthreads();
    }

    // epilogue: dy -> sDw (cols 0..2, fp32) and pw_h (cols 3.., fp16), +bias
    #pragma unroll
    for (int i = 0; i < 12; i++) {
        int t = wid + 8 * i;
        if (t < 91) {
            int mt = t / 13, nt = t % 13;
            int r1 = mt * 16 + (lane >> 2), r2 = r1 + 8;
            int c1 = nt * 8 + 2 * (lane & 3), c2 = c1 + 1;
            float d0 = acc1[i][0] + sBias[c1];
            float d1 = acc1[i][1] + sBias[c2];
            float d2 = acc1[i][2] + sBias[c1];
            float d3 = acc1[i][3] + sBias[c2];
            if (c1 < 3) { if (r1 < NN) sDw[r1 * 4 + c1] = d0;
                          if (r2 < NN) sDw[r2 * 4 + c1] = d2; }
            else { pw_h[r1 * PWS + c1 - 3] = __float2half(d0);
                   pw_h[r2 * PWS + c1 - 3] = __float2half(d2); }
            if (c2 < 3) { if (r1 < NN) sDw[r1 * 4 + c2] = d1;
                          if (r2 < NN) sDw[r2 * 4 + c2] = d3; }
            else { pw_h[r1 * PWS + c2 - 3] = __float2half(d1);
                   pw_h[r2 * PWS + c2 - 3] = __float2half(d3); }
        }
    }
    __syncthreads();

    // =========================================================
    // Stage 2: depth^T[c][m] = relu(conv3(v))  (fp16), plus k'-pad zeroing
    // =========================================================
    #pragma unroll
    for (int it = 0; it < 20; it++) {          // zero sDT cols 100..119
        int idx = tid + it * 256;              // 5120
        sDT[(idx / 20) * DTS + 100 + (idx % 20)] = __float2half(0.0f);
    }
    #pragma unroll 1
    for (int it = 0; it < 25; it++) {
        int idx = tid + it * 256;              // 6400 (r,g) pairs
        int r = idx >> 6, g = idx & 63;
        float d0 = sDw[r * 4 + 0];
        float d1 = sDw[r * 4 + 1];
        float d2 = sDw[r * 4 + 2];
        const float* vr = v + r * CC;
        #pragma unroll
        for (int j = 0; j < 4; j++) {
            int c = g + 64 * j;
            float vc = vr[c];
            float vm = __shfl_up_sync(0xffffffffu, vc, 1);
            float vp = __shfl_down_sync(0xffffffffu, vc, 1);
            if (lane == 0)  vm = (c > 0)   ? vr[c - 1] : 0.0f;
            if (lane == 31) vp = (c < 255) ? vr[c + 1] : 0.0f;
            float o = fmaxf(d0 * vm + d1 * vc + d2 * vp, 0.0f);
            sDT[c * DTS + r] = __float2half(o);
        }
    }
    __syncthreads();

    // =========================================================
    // Stage 3+4: out = pw @ depth, fused LayerNorm per m16 band.
    // warp owns n columns [wid*32, wid*32+32); loop m_t bands.
    // =========================================================
    #pragma unroll 1
    for (int mt = 0; mt < 7; mt++) {
        float acc[4][4];
        #pragma unroll
        for (int t = 0; t < 4; t++)
            #pragma unroll
            for (int j = 0; j < 4; j++) acc[t][j] = 0.0f;

        uint32_t abase = sPW_u + ((mt * 16 + (lane & 15)) * PWS + (lane >> 4) * 8) * 2;
        int brow = wid * 32 + ((lane >> 4) & 1) * 8 + (lane & 7);
        uint32_t bbase = sDT_u + (brow * DTS + ((lane >> 3) & 1) * 8) * 2;

        #pragma unroll
        for (int ks = 0; ks < 7; ks++) {
            uint32_t a0, a1, a2, a3;
            uint32_t p0, p1, p2, p3, q0, q1, q2, q3;
            ldsm4(a0, a1, a2, a3, abase + ks * 32);
            ldsm4(p0, p1, p2, p3, bbase + ks * 32);
            ldsm4(q0, q1, q2, q3, bbase + 16 * DTS * 2 + ks * 32);
            mma16816(acc[0], a0, a1, a2, a3, p0, p1);
            mma16816(acc[1], a0, a1, a2, a3, p2, p3);
            mma16816(acc[2], a0, a1, a2, a3, q0, q1);
            mma16816(acc[3], a0, a1, a2, a3, q2, q3);
        }

        // per-row (32-col slice) partial sums
        float s1 = 0.f, q1s = 0.f, s2 = 0.f, q2s = 0.f;
        #pragma unroll
        for (int t = 0; t < 4; t++) {
            s1  += acc[t][0] + acc[t][1];
            q1s += acc[t][0] * acc[t][0] + acc[t][1] * acc[t][1];
            s2  += acc[t][2] + acc[t][3];
            q2s += acc[t][2] * acc[t][2] + acc[t][3] * acc[t][3];
        }
        #pragma unroll
        for (int off = 1; off <= 2; off <<= 1) {
            s1  += __shfl_xor_sync(0xffffffffu, s1,  off);
            q1s += __shfl_xor_sync(0xffffffffu, q1s, off);
            s2  += __shfl_xor_sync(0xffffffffu, s2,  off);
            q2s += __shfl_xor_sync(0xffffffffu, q2s, off);
        }
        int p = mt & 1;
        if ((lane & 3) == 0) {
            int rl = lane >> 2;
            float* rr = sRed + ((p * 16 + rl) * 8 + wid) * 2;
            rr[0] = s1; rr[1] = q1s;
            float* rr2 = sRed + ((p * 16 + rl + 8) * 8 + wid) * 2;
            rr2[0] = s2; rr2[1] = q2s;
        }
        __syncthreads();

        int rl1 = lane >> 2;
        float S1 = 0.f, Q1 = 0.f, S2 = 0.f, Q2 = 0.f;
        #pragma unroll
        for (int w = 0; w < 8; w++) {
            const float* rr = sRed + ((p * 16 + rl1) * 8 + w) * 2;
            S1 += rr[0]; Q1 += rr[1];
            const float* rr2 = sRed + ((p * 16 + rl1 + 8) * 8 + w) * 2;
            S2 += rr2[0]; Q2 += rr2[1];
        }
        float mu1 = S1 * (1.0f / 256.0f);
        float v1  = Q1 * (1.0f / 256.0f) - mu1 * mu1;
        float iv1 = rsqrtf(v1 + 1e-5f);
        float mu2 = S2 * (1.0f / 256.0f);
        float v2  = Q2 * (1.0f / 256.0f) - mu2 * mu2;
        float iv2 = rsqrtf(v2 + 1e-5f);

        int r1 = mt * 16 + rl1, r2 = r1 + 8;
        if (r1 < NN) {
            #pragma unroll
            for (int t = 0; t < 4; t++) {
                int col = wid * 32 + t * 8 + 2 * (lane & 3);
                outp[r1 * CC + col]     = (acc[t][0] - mu1) * iv1 * g8[2 * t]     + be8[2 * t];
                outp[r1 * CC + col + 1] = (acc[t][1] - mu1) * iv1 * g8[2 * t + 1] + be8[2 * t + 1];
            }
        }
        if (r2 < NN) {
            #pragma unroll
            for (int t = 0; t < 4; t++) {
                int col = wid * 32 + t * 8 + 2 * (lane & 3);
                outp[r2 * CC + col]     = (acc[t][2] - mu2) * iv2 * g8[2 * t]     + be8[2 * t];
                outp[r2 * CC + col + 1] = (acc[t][3] - mu2) * iv2 * g8[2 * t + 1] + be8[2 * t + 1];
            }
        }
    }
}

extern "C" void kernel_launch(void* const* d_in, const int* in_sizes, int n_in,
                              void* d_out, int out_size) {
    const float* q     = (const float*)d_in[0];
    const float* v     = (const float*)d_in[1];
    const float* W     = (const float*)d_in[2];
    const float* bias  = (const float*)d_in[3];
    const float* gamma = (const float*)d_in[4];
    const float* beta  = (const float*)d_in[5];
    float* out = (float*)d_out;

    cudaFuncSetAttribute(dysepconv_mma_kernel,
                         cudaFuncAttributeMaxDynamicSharedMemorySize, SMEM_TOTAL);
    dysepconv_mma_kernel<<<BB, 256, SMEM_TOTAL>>>(q, v, W, bias, gamma, beta, out);
}

// round 5
// speedup vs baseline: 2.0975x; 1.7072x over previous
#include <cuda_runtime.h>
#include <cuda_fp16.h>
#include <cstdint>

#define BB 512
#define NN 100
#define CC 256
#define NJ 103

#define QS  72     // stage q/W stride (halfs) -> 144B, conflict-free ldmatrix
#define PWS 120    // pw stride (halfs)
#define DTS 264    // depth stride (halfs) -> 528B, conflict-free ldmatrix.trans

#define OFF_PW   0
#define OFF_DW   26880
#define OFF_BIAS 28480
#define OFF_RED  28896
#define OFF_STG  30976
#define BUFQ     16128                    // 112*72*2 bytes per matrix buffer
#define BUFPAIR  32256                    // q + W
#define SMEM_TOTAL (OFF_STG + 2*BUFPAIR)  // 95488 B  (depth 112*264*2=59136 fits region)

__device__ __half gQh[(size_t)BB * 112 * 256];   // zero-init: rows 100..111 stay 0
__device__ __half gWT[112 * 256];                // zero-init: rows 103..111 stay 0

// ---------------- pre-convert kernel ----------------
__global__ void __launch_bounds__(256)
cvt_kernel(const float* __restrict__ gq, const float* __restrict__ gW) {
    int b = blockIdx.x;
    if (b < BB) {
        const float* q = gq + (size_t)b * NN * CC;
        __half* dst = gQh + (size_t)b * 112 * 256;
        #pragma unroll
        for (int it = 0; it < 25; it++) {
            int idx = threadIdx.x + it * 256;       // 6400 float4 groups
            int r = idx >> 6, c4 = idx & 63;
            float4 f = *(const float4*)&q[r * CC + c4 * 4];
            __half2 h0 = __floats2half2_rn(f.x, f.y);
            __half2 h1 = __floats2half2_rn(f.z, f.w);
            *(uint2*)&dst[r * 256 + c4 * 4] =
                make_uint2(*(uint32_t*)&h0, *(uint32_t*)&h1);
        }
    } else {
        int n = threadIdx.x;
        if (n < NJ) {
            #pragma unroll 8
            for (int k = 0; k < 256; k++)
                gWT[n * 256 + k] = __float2half(gW[k * NJ + n]);
        }
    }
}

// ---------------- helpers ----------------
__device__ __forceinline__ void cp16(uint32_t dst, const void* src) {
    asm volatile("cp.async.cg.shared.global [%0], [%1], 16;" :: "r"(dst), "l"(src));
}
__device__ __forceinline__ void cp_commit() {
    asm volatile("cp.async.commit_group;" ::: "memory");
}
template <int N> __device__ __forceinline__ void cp_wait() {
    asm volatile("cp.async.wait_group %0;" :: "n"(N) : "memory");
}
__device__ __forceinline__ void ldsm4(uint32_t& r0, uint32_t& r1, uint32_t& r2, uint32_t& r3, uint32_t a) {
    asm volatile("ldmatrix.sync.aligned.m8n8.x4.shared.b16 {%0,%1,%2,%3}, [%4];"
                 : "=r"(r0), "=r"(r1), "=r"(r2), "=r"(r3) : "r"(a));
}
__device__ __forceinline__ void ldsm4t(uint32_t& r0, uint32_t& r1, uint32_t& r2, uint32_t& r3, uint32_t a) {
    asm volatile("ldmatrix.sync.aligned.m8n8.x4.trans.shared.b16 {%0,%1,%2,%3}, [%4];"
                 : "=r"(r0), "=r"(r1), "=r"(r2), "=r"(r3) : "r"(a));
}
__device__ __forceinline__ void ldsm2(uint32_t& r0, uint32_t& r1, uint32_t a) {
    asm volatile("ldmatrix.sync.aligned.m8n8.x2.shared.b16 {%0,%1}, [%2];"
                 : "=r"(r0), "=r"(r1) : "r"(a));
}
__device__ __forceinline__ void mma16816(float* c, uint32_t a0, uint32_t a1, uint32_t a2, uint32_t a3,
                                         uint32_t b0, uint32_t b1) {
    asm volatile("mma.sync.aligned.m16n8k16.row.col.f32.f16.f16.f32 "
                 "{%0,%1,%2,%3}, {%4,%5,%6,%7}, {%8,%9}, {%0,%1,%2,%3};"
                 : "+f"(c[0]), "+f"(c[1]), "+f"(c[2]), "+f"(c[3])
                 : "r"(a0), "r"(a1), "r"(a2), "r"(a3), "r"(b0), "r"(b1));
}

// ---------------- main kernel ----------------
__global__ void __launch_bounds__(256, 2)
dysepconv_mma2_kernel(const float* __restrict__ gv,
                      const float* __restrict__ gbias,
                      const float* __restrict__ ggamma,
                      const float* __restrict__ gbeta,
                      float* __restrict__ gout)
{
    extern __shared__ char sm[];
    __half* pw_h  = (__half*)(sm + OFF_PW);
    float*  sDw   = (float*) (sm + OFF_DW);
    float*  sBias = (float*) (sm + OFF_BIAS);
    float*  sRed  = (float*) (sm + OFF_RED);
    __half* sDT   = (__half*)(sm + OFF_STG);

    const int tid  = threadIdx.x;
    const int lane = tid & 31;
    const int wid  = tid >> 5;
    const int b    = blockIdx.x;

    const float* v    = gv + (size_t)b * NN * CC;
    float*       outp = gout + (size_t)b * NN * CC;

    const uint32_t sBase = (uint32_t)__cvta_generic_to_shared(sm);
    const uint32_t sSTG  = sBase + OFF_STG;
    const uint32_t sPW_u = sBase + OFF_PW;
    const uint32_t sDT_u = sBase + OFF_STG;

    if (tid < 104) sBias[tid] = (tid < NJ) ? gbias[tid] : 0.0f;
    // zero pw pad cols 100..119
    #pragma unroll
    for (int it = 0; it < 9; it++) {
        int idx = tid + it * 256;
        if (idx < 112 * 20) pw_h[(idx / 20) * PWS + 100 + (idx % 20)] = __float2half(0.0f);
    }
    // gamma/beta for this lane's 8 output columns
    float g8[8], be8[8];
    #pragma unroll
    for (int t = 0; t < 4; t++) {
        int col = wid * 32 + t * 8 + 2 * (lane & 3);
        g8[2 * t]     = ggamma[col];     g8[2 * t + 1]  = ggamma[col + 1];
        be8[2 * t]    = gbeta[col];      be8[2 * t + 1] = gbeta[col + 1];
    }

    // ---------- stage 1: dy = q @ W + bias, cp.async double-buffered ----------
    const __half* srcQ = gQh + (size_t)b * 112 * 256;

    auto load_chunk = [&](int kc, int bufsel) {
        uint32_t dq = sSTG + bufsel * BUFPAIR;
        uint32_t dw = dq + BUFQ;
        #pragma unroll
        for (int it = 0; it < 4; it++) {
            int idx = tid + it * 256;
            if (idx < 896) {
                int row = idx >> 3, seg = idx & 7;
                cp16(dq + (row * QS + seg * 8) * 2, srcQ + row * 256 + kc + seg * 8);
            }
        }
        #pragma unroll
        for (int it = 0; it < 4; it++) {
            int idx = tid + it * 256;
            if (idx < 896) {
                int row = idx >> 3, seg = idx & 7;
                cp16(dw + (row * QS + seg * 8) * 2, gWT + row * 256 + kc + seg * 8);
            }
        }
        cp_commit();
    };

    float acc1[7][2][4];
    #pragma unroll
    for (int mt = 0; mt < 7; mt++)
        #pragma unroll
        for (int j = 0; j < 2; j++)
            #pragma unroll
            for (int t = 0; t < 4; t++) acc1[mt][j][t] = 0.0f;

    const bool has2 = (wid < 5);
    load_chunk(0, 0);

    #pragma unroll 1
    for (int ch = 0; ch < 4; ch++) {
        if (ch < 3) load_chunk((ch + 1) * 64, (ch + 1) & 1);
        if (ch < 3) cp_wait<1>(); else cp_wait<0>();
        __syncthreads();

        uint32_t bufoff = (ch & 1) * BUFPAIR;
        uint32_t ab  = sSTG + bufoff + ((lane & 15) * QS + (lane >> 4) * 8) * 2;
        uint32_t bb0 = sSTG + bufoff + BUFQ + ((wid * 8 + (lane & 7)) * QS + ((lane >> 3) & 1) * 8) * 2;
        uint32_t bb1 = bb0 + (8 * 8) * QS * 2;   // nt = wid+8

        #pragma unroll
        for (int ks = 0; ks < 4; ks++) {
            uint32_t b0, b1, c0, c1;
            ldsm2(b0, b1, bb0 + ks * 32);
            if (has2) ldsm2(c0, c1, bb1 + ks * 32);
            #pragma unroll
            for (int mt = 0; mt < 7; mt++) {
                uint32_t a0, a1, a2, a3;
                ldsm4(a0, a1, a2, a3, ab + mt * 16 * QS * 2 + ks * 32);
                mma16816(acc1[mt][0], a0, a1, a2, a3, b0, b1);
                if (has2) mma16816(acc1[mt][1], a0, a1, a2, a3, c0, c1);
            }
        }
        __syncthreads();
    }

    // epilogue: dy -> sDw (cols 0..2) and pw_h (cols 3..), +bias
    #pragma unroll
    for (int mt = 0; mt < 7; mt++) {
        #pragma unroll
        for (int j = 0; j < 2; j++) {
            if (j == 1 && !has2) break;
            int nt = wid + 8 * j;
            int r1 = mt * 16 + (lane >> 2), r2 = r1 + 8;
            int c1 = nt * 8 + 2 * (lane & 3), c2 = c1 + 1;
            float d0 = acc1[mt][j][0] + sBias[c1];
            float d1 = acc1[mt][j][1] + sBias[c2];
            float d2 = acc1[mt][j][2] + sBias[c1];
            float d3 = acc1[mt][j][3] + sBias[c2];
            if (c1 < 3) { if (r1 < NN) sDw[r1 * 4 + c1] = d0;
                          if (r2 < NN) sDw[r2 * 4 + c1] = d2; }
            else { pw_h[r1 * PWS + c1 - 3] = __float2half(d0);
                   pw_h[r2 * PWS + c1 - 3] = __float2half(d2); }
            if (c2 < 3) { if (r1 < NN) sDw[r1 * 4 + c2] = d1;
                          if (r2 < NN) sDw[r2 * 4 + c2] = d3; }
            else { pw_h[r1 * PWS + c2 - 3] = __float2half(d1);
                   pw_h[r2 * PWS + c2 - 3] = __float2half(d3); }
        }
    }
    __syncthreads();

    // ---------- stage 2: depth[m][c] = relu(conv3(v)) -> fp16, rows 100..111 zero ----------
    #pragma unroll
    for (int it = 0; it < 4; it++) {
        int idx = tid + it * 256;
        if (idx < 792) {        // 12 rows * 66 uint2
            int row = 100 + idx / 66, col = (idx % 66) * 4;
            *(uint2*)&sDT[row * DTS + col] = make_uint2(0u, 0u);
        }
    }
    #pragma unroll 1
    for (int it = 0; it < 25; it++) {
        int idx = tid + it * 256;
        int r = idx >> 6, g = idx & 63;
        int c0 = g * 4;
        float d0 = sDw[r * 4 + 0];
        float d1 = sDw[r * 4 + 1];
        float d2 = sDw[r * 4 + 2];
        const float* vr = v + r * CC;
        float4 vv = *(const float4*)&vr[c0];
        float vl = (c0 > 0)   ? vr[c0 - 1] : 0.0f;
        float vh = (c0 < 252) ? vr[c0 + 4] : 0.0f;
        float ox = fmaxf(d0 * vl   + d1 * vv.x + d2 * vv.y, 0.0f);
        float oy = fmaxf(d0 * vv.x + d1 * vv.y + d2 * vv.z, 0.0f);
        float oz = fmaxf(d0 * vv.y + d1 * vv.z + d2 * vv.w, 0.0f);
        float ow = fmaxf(d0 * vv.z + d1 * vv.w + d2 * vh,   0.0f);
        __half2 h0 = __floats2half2_rn(ox, oy);
        __half2 h1 = __floats2half2_rn(oz, ow);
        *(uint2*)&sDT[r * DTS + c0] = make_uint2(*(uint32_t*)&h0, *(uint32_t*)&h1);
    }
    __syncthreads();

    // ---------- stage 3+4: out = pw @ depth, fused LayerNorm per m16 band ----------
    uint32_t apw_base = sPW_u + ((lane & 15) * PWS + (lane >> 4) * 8) * 2;
    uint32_t bb = sDT_u + (((lane & 7) + ((lane >> 3) & 1) * 8) * DTS
                           + wid * 32 + (lane >> 4) * 8) * 2;

    #pragma unroll 1
    for (int mt = 0; mt < 7; mt++) {
        float acc[4][4];
        #pragma unroll
        for (int t = 0; t < 4; t++)
            #pragma unroll
            for (int j = 0; j < 4; j++) acc[t][j] = 0.0f;

        uint32_t apw = apw_base + mt * 16 * PWS * 2;

        #pragma unroll
        for (int ks = 0; ks < 7; ks++) {
            uint32_t a0, a1, a2, a3;
            uint32_t p0, p1, p2, p3, q0, q1, q2, q3;
            ldsm4(a0, a1, a2, a3, apw + ks * 32);
            ldsm4t(p0, p1, p2, p3, bb + ks * 16 * DTS * 2);
            ldsm4t(q0, q1, q2, q3, bb + ks * 16 * DTS * 2 + 32);
            mma16816(acc[0], a0, a1, a2, a3, p0, p1);
            mma16816(acc[1], a0, a1, a2, a3, p2, p3);
            mma16816(acc[2], a0, a1, a2, a3, q0, q1);
            mma16816(acc[3], a0, a1, a2, a3, q2, q3);
        }

        float s1 = 0.f, q1s = 0.f, s2 = 0.f, q2s = 0.f;
        #pragma unroll
        for (int t = 0; t < 4; t++) {
            s1  += acc[t][0] + acc[t][1];
            q1s += acc[t][0] * acc[t][0] + acc[t][1] * acc[t][1];
            s2  += acc[t][2] + acc[t][3];
            q2s += acc[t][2] * acc[t][2] + acc[t][3] * acc[t][3];
        }
        #pragma unroll
        for (int off = 1; off <= 2; off <<= 1) {
            s1  += __shfl_xor_sync(0xffffffffu, s1,  off);
            q1s += __shfl_xor_sync(0xffffffffu, q1s, off);
            s2  += __shfl_xor_sync(0xffffffffu, s2,  off);
            q2s += __shfl_xor_sync(0xffffffffu, q2s, off);
        }
        int p = mt & 1;
        if ((lane & 3) == 0) {
            int rl = lane >> 2;
            float* rr = sRed + ((p * 16 + rl) * 8 + wid) * 2;
            rr[0] = s1; rr[1] = q1s;
            float* rr2 = sRed + ((p * 16 + rl + 8) * 8 + wid) * 2;
            rr2[0] = s2; rr2[1] = q2s;
        }
        __syncthreads();

        int rl1 = lane >> 2;
        float S1 = 0.f, Q1 = 0.f, S2 = 0.f, Q2 = 0.f;
        #pragma unroll
        for (int w = 0; w < 8; w++) {
            const float* rr = sRed + ((p * 16 + rl1) * 8 + w) * 2;
            S1 += rr[0]; Q1 += rr[1];
            const float* rr2 = sRed + ((p * 16 + rl1 + 8) * 8 + w) * 2;
            S2 += rr2[0]; Q2 += rr2[1];
        }
        float mu1 = S1 * (1.0f / 256.0f);
        float va1 = Q1 * (1.0f / 256.0f) - mu1 * mu1;
        float iv1 = rsqrtf(va1 + 1e-5f);
        float mu2 = S2 * (1.0f / 256.0f);
        float va2 = Q2 * (1.0f / 256.0f) - mu2 * mu2;
        float iv2 = rsqrtf(va2 + 1e-5f);

        int r1 = mt * 16 + rl1, r2 = r1 + 8;
        if (r1 < NN) {
            #pragma unroll
            for (int t = 0; t < 4; t++) {
                int col = wid * 32 + t * 8 + 2 * (lane & 3);
                float2 o;
                o.x = (acc[t][0] - mu1) * iv1 * g8[2 * t]     + be8[2 * t];
                o.y = (acc[t][1] - mu1) * iv1 * g8[2 * t + 1] + be8[2 * t + 1];
                *(float2*)&outp[r1 * CC + col] = o;
            }
        }
        if (r2 < NN) {
            #pragma unroll
            for (int t = 0; t < 4; t++) {
                int col = wid * 32 + t * 8 + 2 * (lane & 3);
                float2 o;
                o.x = (acc[t][2] - mu2) * iv2 * g8[2 * t]     + be8[2 * t];
                o.y = (acc[t][3] - mu2) * iv2 * g8[2 * t + 1] + be8[2 * t + 1];
                *(float2*)&outp[r2 * CC + col] = o;
            }
        }
    }
}

extern "C" void kernel_launch(void* const* d_in, const int* in_sizes, int n_in,
                              void* d_out, int out_size) {
    const float* q     = (const float*)d_in[0];
    const float* v     = (const float*)d_in[1];
    const float* W     = (const float*)d_in[2];
    const float* bias  = (const float*)d_in[3];
    const float* gamma = (const float*)d_in[4];
    const float* beta  = (const float*)d_in[5];
    float* out = (float*)d_out;

    cvt_kernel<<<BB + 1, 256>>>(q, W);
    cudaFuncSetAttribute(dysepconv_mma2_kernel,
                         cudaFuncAttributeMaxDynamicSharedMemorySize, SMEM_TOTAL);
    dysepconv_mma2_kernel<<<BB, 256, SMEM_TOTAL>>>(v, bias, gamma, beta, out);
}

// round 6
// speedup vs baseline: 3.1010x; 1.4784x over previous
#include <cuda_runtime.h>
#include <cuda_fp16.h>
#include <cstdint>

#define BB 512
#define NN 100
#define CC 256
#define NJ 103

#define QS  72     // stage q/W stride (halfs) -> 144B, conflict-free ldmatrix
#define PWS 120    // pw stride (halfs)
#define DTS 264    // depth stride (halfs) -> 528B, conflict-free ldmatrix.trans

#define OFF_PW   0
#define OFF_DW   26880
#define OFF_BIAS 28480
#define OFF_RED  28896
#define OFF_STG  30976
#define BUFQ     16128                    // 112*72*2 bytes per matrix buffer
#define BUFPAIR  32256                    // q + W
#define SMEM_TOTAL (OFF_STG + 2*BUFPAIR)  // 95488 B  (depth 112*264*2=59136 fits region)

__device__ __half gWT[112 * 256];         // zero-init: rows 103..111 stay 0

// ---------------- tiny W transpose+convert kernel ----------------
__global__ void __launch_bounds__(128)
cvtW_kernel(const float* __restrict__ gW) {
    int k = blockIdx.x;        // 0..255
    int n = threadIdx.x;       // 0..127
    if (n < NJ) gWT[n * 256 + k] = __float2half(gW[k * NJ + n]);
}

// ---------------- helpers ----------------
__device__ __forceinline__ void cp16(uint32_t dst, const void* src) {
    asm volatile("cp.async.cg.shared.global [%0], [%1], 16;" :: "r"(dst), "l"(src));
}
__device__ __forceinline__ void cp_commit() {
    asm volatile("cp.async.commit_group;" ::: "memory");
}
template <int N> __device__ __forceinline__ void cp_wait() {
    asm volatile("cp.async.wait_group %0;" :: "n"(N) : "memory");
}
__device__ __forceinline__ void ldsm4(uint32_t& r0, uint32_t& r1, uint32_t& r2, uint32_t& r3, uint32_t a) {
    asm volatile("ldmatrix.sync.aligned.m8n8.x4.shared.b16 {%0,%1,%2,%3}, [%4];"
                 : "=r"(r0), "=r"(r1), "=r"(r2), "=r"(r3) : "r"(a));
}
__device__ __forceinline__ void ldsm4t(uint32_t& r0, uint32_t& r1, uint32_t& r2, uint32_t& r3, uint32_t a) {
    asm volatile("ldmatrix.sync.aligned.m8n8.x4.trans.shared.b16 {%0,%1,%2,%3}, [%4];"
                 : "=r"(r0), "=r"(r1), "=r"(r2), "=r"(r3) : "r"(a));
}
__device__ __forceinline__ void ldsm2(uint32_t& r0, uint32_t& r1, uint32_t a) {
    asm volatile("ldmatrix.sync.aligned.m8n8.x2.shared.b16 {%0,%1}, [%2];"
                 : "=r"(r0), "=r"(r1) : "r"(a));
}
__device__ __forceinline__ void mma16816(float* c, uint32_t a0, uint32_t a1, uint32_t a2, uint32_t a3,
                                         uint32_t b0, uint32_t b1) {
    asm volatile("mma.sync.aligned.m16n8k16.row.col.f32.f16.f16.f32 "
                 "{%0,%1,%2,%3}, {%4,%5,%6,%7}, {%8,%9}, {%0,%1,%2,%3};"
                 : "+f"(c[0]), "+f"(c[1]), "+f"(c[2]), "+f"(c[3])
                 : "r"(a0), "r"(a1), "r"(a2), "r"(a3), "r"(b0), "r"(b1));
}

// ---------------- main kernel ----------------
__global__ void __launch_bounds__(256, 2)
dysepconv_mma3_kernel(const float* __restrict__ gq,
                      const float* __restrict__ gv,
                      const float* __restrict__ gbias,
                      const float* __restrict__ ggamma,
                      const float* __restrict__ gbeta,
                      float* __restrict__ gout)
{
    extern __shared__ char sm[];
    __half* pw_h  = (__half*)(sm + OFF_PW);
    float*  sDw   = (float*) (sm + OFF_DW);
    float*  sBias = (float*) (sm + OFF_BIAS);
    float*  sRed  = (float*) (sm + OFF_RED);
    __half* sDT   = (__half*)(sm + OFF_STG);

    const int tid  = threadIdx.x;
    const int lane = tid & 31;
    const int wid  = tid >> 5;
    const int b    = blockIdx.x;

    const float* qsrc = gq + (size_t)b * NN * CC;
    const float* v    = gv + (size_t)b * NN * CC;
    float*       outp = gout + (size_t)b * NN * CC;

    const uint32_t sBase = (uint32_t)__cvta_generic_to_shared(sm);
    const uint32_t sSTG  = sBase + OFF_STG;
    const uint32_t sPW_u = sBase + OFF_PW;
    const uint32_t sDT_u = sBase + OFF_STG;

    if (tid < 104) sBias[tid] = (tid < NJ) ? gbias[tid] : 0.0f;
    // zero pw pad cols 100..119
    #pragma unroll
    for (int it = 0; it < 9; it++) {
        int idx = tid + it * 256;
        if (idx < 112 * 20) pw_h[(idx / 20) * PWS + 100 + (idx % 20)] = __float2half(0.0f);
    }
    // gamma/beta for this lane's 8 output columns
    float g8[8], be8[8];
    #pragma unroll
    for (int t = 0; t < 4; t++) {
        int col = wid * 32 + t * 8 + 2 * (lane & 3);
        g8[2 * t]     = ggamma[col];     g8[2 * t + 1]  = ggamma[col + 1];
        be8[2 * t]    = gbeta[col];      be8[2 * t + 1] = gbeta[col + 1];
    }

    // ---------- stage 1: dy = q @ W + bias ----------
    // q: LDG fp32 -> regs -> cvt fp16 -> STS (prefetched one chunk ahead)
    // W: cp.async from pre-converted gWT
    float4 qreg[7];
    const int qrow = -1;  // placeholder (rows derived per-iteration)

    auto ldg_q = [&](int kc) {
        #pragma unroll
        for (int it = 0; it < 7; it++) {
            int idx = tid + it * 256;            // 0..1791
            int r = idx >> 4, seg = idx & 15;
            qreg[it] = (r < NN) ? *(const float4*)&qsrc[r * CC + kc + seg * 4]
                                : make_float4(0.f, 0.f, 0.f, 0.f);
        }
    };
    auto sts_q = [&](int bufsel) {
        __half* dstq = (__half*)(sm + OFF_STG + bufsel * BUFPAIR);
        #pragma unroll
        for (int it = 0; it < 7; it++) {
            int idx = tid + it * 256;
            int r = idx >> 4, seg = idx & 15;
            __half2 h0 = __floats2half2_rn(qreg[it].x, qreg[it].y);
            __half2 h1 = __floats2half2_rn(qreg[it].z, qreg[it].w);
            *(uint2*)&dstq[r * QS + seg * 4] =
                make_uint2(*(uint32_t*)&h0, *(uint32_t*)&h1);
        }
    };
    auto cp_w = [&](int kc, int bufsel) {
        uint32_t dw = sSTG + bufsel * BUFPAIR + BUFQ;
        #pragma unroll
        for (int it = 0; it < 4; it++) {
            int idx = tid + it * 256;
            if (idx < 896) {
                int row = idx >> 3, seg = idx & 7;
                cp16(dw + (row * QS + seg * 8) * 2, gWT + row * 256 + kc + seg * 8);
            }
        }
        cp_commit();
    };

    float acc1[7][2][4];
    #pragma unroll
    for (int mt = 0; mt < 7; mt++)
        #pragma unroll
        for (int j = 0; j < 2; j++)
            #pragma unroll
            for (int t = 0; t < 4; t++) acc1[mt][j][t] = 0.0f;

    const bool has2 = (wid < 5);

    // prologue: fill buffer 0
    ldg_q(0);
    cp_w(0, 0);
    sts_q(0);
    cp_wait<0>();
    __syncthreads();

    #pragma unroll 1
    for (int ch = 0; ch < 4; ch++) {
        // issue next chunk's loads early (latency hidden under MMAs)
        if (ch < 3) {
            ldg_q((ch + 1) * 64);
            cp_w((ch + 1) * 64, (ch + 1) & 1);
        }

        uint32_t bufoff = (ch & 1) * BUFPAIR;
        uint32_t ab  = sSTG + bufoff + ((lane & 15) * QS + (lane >> 4) * 8) * 2;
        uint32_t bb0 = sSTG + bufoff + BUFQ + ((wid * 8 + (lane & 7)) * QS + ((lane >> 3) & 1) * 8) * 2;
        uint32_t bb1 = bb0 + (8 * 8) * QS * 2;   // nt = wid+8

        #pragma unroll
        for (int ks = 0; ks < 4; ks++) {
            uint32_t b0, b1, c0, c1;
            ldsm2(b0, b1, bb0 + ks * 32);
            if (has2) ldsm2(c0, c1, bb1 + ks * 32);
            #pragma unroll
            for (int mt = 0; mt < 7; mt++) {
                uint32_t a0, a1, a2, a3;
                ldsm4(a0, a1, a2, a3, ab + mt * 16 * QS * 2 + ks * 32);
                mma16816(acc1[mt][0], a0, a1, a2, a3, b0, b1);
                if (has2) mma16816(acc1[mt][1], a0, a1, a2, a3, c0, c1);
            }
        }

        if (ch < 3) {
            sts_q((ch + 1) & 1);
            cp_wait<0>();
        }
        __syncthreads();
    }

    // epilogue: dy -> sDw (cols 0..2) and pw_h (cols 3..), +bias
    #pragma unroll
    for (int mt = 0; mt < 7; mt++) {
        #pragma unroll
        for (int j = 0; j < 2; j++) {
            if (j == 1 && !has2) break;
            int nt = wid + 8 * j;
            int r1 = mt * 16 + (lane >> 2), r2 = r1 + 8;
            int c1 = nt * 8 + 2 * (lane & 3), c2 = c1 + 1;
            float d0 = acc1[mt][j][0] + sBias[c1];
            float d1 = acc1[mt][j][1] + sBias[c2];
            float d2 = acc1[mt][j][2] + sBias[c1];
            float d3 = acc1[mt][j][3] + sBias[c2];
            if (c1 < 3) { if (r1 < NN) sDw[r1 * 4 + c1] = d0;
                          if (r2 < NN) sDw[r2 * 4 + c1] = d2; }
            else { pw_h[r1 * PWS + c1 - 3] = __float2half(d0);
                   pw_h[r2 * PWS + c1 - 3] = __float2half(d2); }
            if (c2 < 3) { if (r1 < NN) sDw[r1 * 4 + c2] = d1;
                          if (r2 < NN) sDw[r2 * 4 + c2] = d3; }
            else { pw_h[r1 * PWS + c2 - 3] = __float2half(d1);
                   pw_h[r2 * PWS + c2 - 3] = __float2half(d3); }
        }
    }
    __syncthreads();

    // ---------- stage 2: depth[m][c] = relu(conv3(v)) -> fp16, rows 100..111 zero ----------
    #pragma unroll
    for (int it = 0; it < 4; it++) {
        int idx = tid + it * 256;
        if (idx < 792) {        // 12 rows * 66 uint2
            int row = 100 + idx / 66, col = (idx % 66) * 4;
            *(uint2*)&sDT[row * DTS + col] = make_uint2(0u, 0u);
        }
    }
    #pragma unroll 1
    for (int it = 0; it < 25; it++) {
        int idx = tid + it * 256;
        int r = idx >> 6, g = idx & 63;
        int c0 = g * 4;
        float d0 = sDw[r * 4 + 0];
        float d1 = sDw[r * 4 + 1];
        float d2 = sDw[r * 4 + 2];
        const float* vr = v + r * CC;
        float4 vv = *(const float4*)&vr[c0];
        float vl = (c0 > 0)   ? vr[c0 - 1] : 0.0f;
        float vh = (c0 < 252) ? vr[c0 + 4] : 0.0f;
        float ox = fmaxf(d0 * vl   + d1 * vv.x + d2 * vv.y, 0.0f);
        float oy = fmaxf(d0 * vv.x + d1 * vv.y + d2 * vv.z, 0.0f);
        float oz = fmaxf(d0 * vv.y + d1 * vv.z + d2 * vv.w, 0.0f);
        float ow = fmaxf(d0 * vv.z + d1 * vv.w + d2 * vh,   0.0f);
        __half2 h0 = __floats2half2_rn(ox, oy);
        __half2 h1 = __floats2half2_rn(oz, ow);
        *(uint2*)&sDT[r * DTS + c0] = make_uint2(*(uint32_t*)&h0, *(uint32_t*)&h1);
    }
    __syncthreads();

    // ---------- stage 3+4: out = pw @ depth, fused LayerNorm per m16 band ----------
    uint32_t apw_base = sPW_u + ((lane & 15) * PWS + (lane >> 4) * 8) * 2;
    uint32_t bb = sDT_u + (((lane & 7) + ((lane >> 3) & 1) * 8) * DTS
                           + wid * 32 + (lane >> 4) * 8) * 2;

    #pragma unroll 1
    for (int mt = 0; mt < 7; mt++) {
        float acc[4][4];
        #pragma unroll
        for (int t = 0; t < 4; t++)
            #pragma unroll
            for (int j = 0; j < 4; j++) acc[t][j] = 0.0f;

        uint32_t apw = apw_base + mt * 16 * PWS * 2;

        #pragma unroll
        for (int ks = 0; ks < 7; ks++) {
            uint32_t a0, a1, a2, a3;
            uint32_t p0, p1, p2, p3, q0, q1, q2, q3;
            ldsm4(a0, a1, a2, a3, apw + ks * 32);
            ldsm4t(p0, p1, p2, p3, bb + ks * 16 * DTS * 2);
            ldsm4t(q0, q1, q2, q3, bb + ks * 16 * DTS * 2 + 32);
            mma16816(acc[0], a0, a1, a2, a3, p0, p1);
            mma16816(acc[1], a0, a1, a2, a3, p2, p3);
            mma16816(acc[2], a0, a1, a2, a3, q0, q1);
            mma16816(acc[3], a0, a1, a2, a3, q2, q3);
        }

        float s1 = 0.f, q1s = 0.f, s2 = 0.f, q2s = 0.f;
        #pragma unroll
        for (int t = 0; t < 4; t++) {
            s1  += acc[t][0] + acc[t][1];
            q1s += acc[t][0] * acc[t][0] + acc[t][1] * acc[t][1];
            s2  += acc[t][2] + acc[t][3];
            q2s += acc[t][2] * acc[t][2] + acc[t][3] * acc[t][3];
        }
        #pragma unroll
        for (int off = 1; off <= 2; off <<= 1) {
            s1  += __shfl_xor_sync(0xffffffffu, s1,  off);
            q1s += __shfl_xor_sync(0xffffffffu, q1s, off);
            s2  += __shfl_xor_sync(0xffffffffu, s2,  off);
            q2s += __shfl_xor_sync(0xffffffffu, q2s, off);
        }
        int p = mt & 1;
        if ((lane & 3) == 0) {
            int rl = lane >> 2;
            float* rr = sRed + ((p * 16 + rl) * 8 + wid) * 2;
            rr[0] = s1; rr[1] = q1s;
            float* rr2 = sRed + ((p * 16 + rl + 8) * 8 + wid) * 2;
            rr2[0] = s2; rr2[1] = q2s;
        }
        __syncthreads();

        int rl1 = lane >> 2;
        float S1 = 0.f, Q1 = 0.f, S2 = 0.f, Q2 = 0.f;
        #pragma unroll
        for (int w = 0; w < 8; w++) {
            const float* rr = sRed + ((p * 16 + rl1) * 8 + w) * 2;
            S1 += rr[0]; Q1 += rr[1];
            const float* rr2 = sRed + ((p * 16 + rl1 + 8) * 8 + w) * 2;
            S2 += rr2[0]; Q2 += rr2[1];
        }
        float mu1 = S1 * (1.0f / 256.0f);
        float va1 = Q1 * (1.0f / 256.0f) - mu1 * mu1;
        float iv1 = rsqrtf(va1 + 1e-5f);
        float mu2 = S2 * (1.0f / 256.0f);
        float va2 = Q2 * (1.0f / 256.0f) - mu2 * mu2;
        float iv2 = rsqrtf(va2 + 1e-5f);

        int r1 = mt * 16 + rl1, r2 = r1 + 8;
        if (r1 < NN) {
            #pragma unroll
            for (int t = 0; t < 4; t++) {
                int col = wid * 32 + t * 8 + 2 * (lane & 3);
                float2 o;
                o.x = (acc[t][0] - mu1) * iv1 * g8[2 * t]     + be8[2 * t];
                o.y = (acc[t][1] - mu1) * iv1 * g8[2 * t + 1] + be8[2 * t + 1];
                *(float2*)&outp[r1 * CC + col] = o;
            }
        }
        if (r2 < NN) {
            #pragma unroll
            for (int t = 0; t < 4; t++) {
                int col = wid * 32 + t * 8 + 2 * (lane & 3);
                float2 o;
                o.x = (acc[t][2] - mu2) * iv2 * g8[2 * t]     + be8[2 * t];
                o.y = (acc[t][3] - mu2) * iv2 * g8[2 * t + 1] + be8[2 * t + 1];
                *(float2*)&outp[r2 * CC + col] = o;
            }
        }
    }
}

extern "C" void kernel_launch(void* const* d_in, const int* in_sizes, int n_in,
                              void* d_out, int out_size) {
    const float* q     = (const float*)d_in[0];
    const float* v     = (const float*)d_in[1];
    const float* W     = (const float*)d_in[2];
    const float* bias  = (const float*)d_in[3];
    const float* gamma = (const float*)d_in[4];
    const float* beta  = (const float*)d_in[5];
    float* out = (float*)d_out;

    cvtW_kernel<<<256, 128>>>(W);
    cudaFuncSetAttribute(dysepconv_mma3_kernel,
                         cudaFuncAttributeMaxDynamicSharedMemorySize, SMEM_TOTAL);
    dysepconv_mma3_kernel<<<BB, 256, SMEM_TOTAL>>>(q, v, bias, gamma, beta, out);
}